// round 9
// baseline (speedup 1.0000x reference)
#include <cuda_runtime.h>
#include <cuda_fp16.h>
#include <cstdint>

#define SD   137
#define HIDN 256
#define AP   264
#define OFF_H   0                      // h fp32 [128][256] = 131072 B
#define OFF_ACT 131072                 // act fp16 [128][264] = 67584 B
#define SMEM_SZ (OFF_ACT + 67584)      // 198656

#define NCHUNK 162
__device__ float g_b0p[HIDN];
__device__ float g_Waug[144*136];
__device__ float g_bias2[144];
// per-chunk fragment-ordered weights: [chunk][wn(4)][p(4)][lane(32)][8 halves]
__device__ __align__(16) __half g_Wf[NCHUNK*4096];

__device__ __forceinline__ float tanh_fast(float x){
    float e = __expf(2.f*x); return 1.f - __fdividef(2.f, e + 1.f);
}
__device__ __forceinline__ uint32_t s2u(const void* p){
    uint32_t a;
    asm("{ .reg .u64 t; cvta.to.shared.u64 t, %1; cvt.u32.u64 %0, t; }" : "=r"(a) : "l"(p));
    return a;
}
#define MMA(d, a0, a1, a2, a3, b0, b1) asm volatile( \
    "mma.sync.aligned.m16n8k16.row.col.f32.f16.f16.f32 " \
    "{%0,%1,%2,%3}, {%4,%5,%6,%7}, {%8,%9}, {%0,%1,%2,%3};" \
    : "+f"((d)[0]), "+f"((d)[1]), "+f"((d)[2]), "+f"((d)[3]) \
    : "r"(a0), "r"(a1), "r"(a2), "r"(a3), "r"(b0), "r"(b1))
#define LDM4(r, addr) asm volatile( \
    "ldmatrix.sync.aligned.m8n8.x4.shared.b16 {%0,%1,%2,%3}, [%4];" \
    : "=r"((r)[0]), "=r"((r)[1]), "=r"((r)[2]), "=r"((r)[3]) : "r"(addr))

// ---------------- prep ----------------
__global__ void prep1(const float* __restrict__ t, const float* __restrict__ W0,
                      const float* __restrict__ b0, const float* __restrict__ bout,
                      const float* __restrict__ lm_in_w, const float* __restrict__ lm_in_b,
                      const float* __restrict__ lm_out_w, const float* __restrict__ lm_out_b,
                      const float* __restrict__ ta_in_b,
                      const float* __restrict__ ta_out_w, const float* __restrict__ ta_out_b){
    int i = threadIdx.x;
    float ang = t[0] * (2.0f * 3.14159265358979323846f / 24.0f);
    g_b0p[i] = b0[i] + sinf(ang)*W0[i*139+137] + cosf(ang)*W0[i*139+138];
    if (i < 128) {
        float a = ta_out_b[i];
        for (int k = 0; k < 128; k++) a += ta_out_w[i*128+k] * ta_in_b[256+k];
        g_bias2[i] = bout[i] + 0.1f*a;
    } else if (i < 136) {
        int j = i - 128;
        float a = lm_out_b[j];
        for (int k = 0; k < 8; k++) a += lm_out_w[j*8+k] * lm_in_b[16+k];
        g_bias2[i] = bout[i] + 0.1f*a;
    } else if (i < 144) {
        g_bias2[i] = (i == 136) ? bout[136] : 0.f;
    }
}

__global__ void prepW(const float* __restrict__ ta_in_w, const float* __restrict__ ta_out_w,
                      const float* __restrict__ lm_in_w, const float* __restrict__ lm_out_w){
    int idx = blockIdx.x*blockDim.x + threadIdx.x;
    if (idx >= 144*136) return;
    int n = idx / 136, k = idx - n*136;
    float v = 0.f;
    if (n < 128 && k < 128) {
        for (int m = 0; m < 128; m++) v += ta_out_w[n*128+m] * ta_in_w[(256+m)*128+k];
    } else if (n >= 128 && n < 136 && k >= 128) {
        for (int m = 0; m < 8; m++) v += lm_out_w[(n-128)*8+m] * lm_in_w[(16+m)*8+(k-128)];
    }
    if (n == k && n < 136) v -= 1.f;
    g_Waug[idx] = 0.1f * v;
}

// weights -> fp16 in per-lane MMA fragment order (one LDG.128 per lane per p)
__global__ void prepW2(const float* __restrict__ W0, const float* __restrict__ W1,
                       const float* __restrict__ W2, const float* __restrict__ Wout){
    int idx = blockIdx.x*blockDim.x + threadIdx.x;
    if (idx >= NCHUNK*4096) return;
    int c = idx >> 12, e = idx & 4095;
    int g = e >> 10, p = (e >> 8) & 3, l = (e >> 3) & 31, j = e & 7;
    int r0 = l >> 2, kk2 = (l & 3) * 2;
    int ni = 2*p + (j >> 2), jj = j & 3;
    int n = 64*g + 8*ni + r0;
    int kloc = kk2 + (jj & 1) + 8*(jj >> 1);

    const float* W; int ldw, nvalid, kmax, ci;
    if (c < 9)        { W = W0; ldw = 139; nvalid = 256; kmax = 137; ci = c; }
    else if (c < 137) { int cc = c - 9, b = cc >> 5, r = cc & 31;
                        W = (r < 16 ? W1 : W2) + b*65536; ci = r & 15;
                        ldw = 256; nvalid = 256; kmax = 256; }
    else if (c < 153) { W = Wout;   ldw = 256; nvalid = 137; kmax = 256; ci = c - 137; }
    else              { W = g_Waug; ldw = 136; nvalid = 144; kmax = 136; ci = c - 153; }
    int k = ci*16 + kloc;
    g_Wf[idx] = __float2half_rn((n < nvalid && k < kmax) ? W[n*ldw + k] : 0.f);
}

// ---------------- barrier-free GEMM: d += act @ Wchunks^T ----------------
__device__ __forceinline__ void gemm(const uint4* __restrict__ bp, int nch,
    uint32_t actu, uint32_t arow0, uint32_t arow1, float (*d)[8][4], int fresh)
{
    if (fresh)
        #pragma unroll
        for (int mi = 0; mi < 2; mi++)
            #pragma unroll
            for (int ni = 0; ni < 8; ni++)
                #pragma unroll
                for (int e = 0; e < 4; e++) d[mi][ni][e] = 0.f;

    #pragma unroll 1
    for (int ci = 0; ci < nch; ci++) {
        uint4 b0 = __ldg(bp);
        uint4 b1 = __ldg(bp + 32);
        uint4 b2 = __ldg(bp + 64);
        uint4 b3 = __ldg(bp + 96);
        bp += 512;
        uint32_t a0[4], a1[4];
        const uint32_t k2 = (uint32_t)(ci * 32);
        LDM4(a0, actu + arow0 + k2);
        LDM4(a1, actu + arow1 + k2);
        MMA(d[0][0], a0[0],a0[1],a0[2],a0[3], b0.x, b0.y);
        MMA(d[1][0], a1[0],a1[1],a1[2],a1[3], b0.x, b0.y);
        MMA(d[0][1], a0[0],a0[1],a0[2],a0[3], b0.z, b0.w);
        MMA(d[1][1], a1[0],a1[1],a1[2],a1[3], b0.z, b0.w);
        MMA(d[0][2], a0[0],a0[1],a0[2],a0[3], b1.x, b1.y);
        MMA(d[1][2], a1[0],a1[1],a1[2],a1[3], b1.x, b1.y);
        MMA(d[0][3], a0[0],a0[1],a0[2],a0[3], b1.z, b1.w);
        MMA(d[1][3], a1[0],a1[1],a1[2],a1[3], b1.z, b1.w);
        MMA(d[0][4], a0[0],a0[1],a0[2],a0[3], b2.x, b2.y);
        MMA(d[1][4], a1[0],a1[1],a1[2],a1[3], b2.x, b2.y);
        MMA(d[0][5], a0[0],a0[1],a0[2],a0[3], b2.z, b2.w);
        MMA(d[1][5], a1[0],a1[1],a1[2],a1[3], b2.z, b2.w);
        MMA(d[0][6], a0[0],a0[1],a0[2],a0[3], b3.x, b3.y);
        MMA(d[1][6], a1[0],a1[1],a1[2],a1[3], b3.x, b3.y);
        MMA(d[0][7], a0[0],a0[1],a0[2],a0[3], b3.z, b3.w);
        MMA(d[1][7], a1[0],a1[1],a1[2],a1[3], b3.z, b3.w);
    }
}

// mode: 0 relu->h+act, 1 tanh->act, 2 tanh(h+.)->h+act, 3 final store
__device__ __forceinline__ void epilogue(int mode, const float* __restrict__ bias,
    float (*d)[8][4], __half* __restrict__ act, float* __restrict__ s_h,
    float* __restrict__ outp, int wm, int wn, int lane)
{
    __syncthreads();                       // all warps done reading act
    const int r0 = lane >> 2, tg = lane & 3;
    #pragma unroll
    for (int mi = 0; mi < 2; mi++)
    #pragma unroll
    for (int ni = 0; ni < 8; ni++)
    #pragma unroll
    for (int e = 0; e < 4; e++) {
        int rr = 32*wm + 16*mi + r0 + (e >> 1)*8;
        int cc = 64*wn + 8*ni + tg*2 + (e & 1);
        float v = d[mi][ni][e];
        if (mode == 3) {
            if (cc < SD) outp[rr*SD + cc] = v + bias[cc];
        } else {
            float x = v + bias[cc];
            if (mode == 0)      x = fmaxf(x, 0.f);
            else if (mode == 1) x = tanh_fast(x);
            else                x = tanh_fast(s_h[rr*256 + cc] + x);
            if (mode != 1) s_h[rr*256 + cc] = x;
            act[rr*AP + cc] = __float2half_rn(x);
        }
    }
    if (mode != 3) __syncthreads();        // act writes visible to next GEMM
}

// ---------------- main ----------------
extern "C" __global__ void __launch_bounds__(512, 1)
ode_mma_full(const float* __restrict__ state,
             const float* __restrict__ blkb1, const float* __restrict__ blkb2,
             float* __restrict__ out)
{
    extern __shared__ char smem[];
    float*  s_h  = (float*)(smem + OFF_H);
    __half* act  = (__half*)(smem + OFF_ACT);
    const uint32_t actu = s2u(act);
    const int tid = threadIdx.x, lane = tid & 31, wid = tid >> 5;
    const int wm = wid & 3, wn = wid >> 2;
    const size_t row0 = (size_t)blockIdx.x * 128;
    const float* st = state + row0 * SD;

    const uint32_t arow0 = (uint32_t)(((32*wm + (lane & 15))*AP + ((lane >> 4) << 3)) * 2);
    const uint32_t arow1 = arow0 + (uint32_t)(16*AP*2);
    const uint4* bw = (const uint4*)g_Wf + wn*128 + lane;

    for (int i = tid; i < 128*144; i += 512) {
        int r = i / 144, c = i - r*144;
        act[r*AP + c] = __float2half_rn(c < SD ? st[r*SD + c] : 0.f);
    }
    __syncthreads();

    float d[2][8][4];

    gemm(bw, 9, actu, arow0, arow1, d, 1);
    epilogue(0, g_b0p, d, act, s_h, nullptr, wm, wn, lane);

    for (int b = 0; b < 4; b++) {
        gemm(bw + (size_t)(9 + 32*b)*512, 16, actu, arow0, arow1, d, 1);
        epilogue(1, blkb1 + b*256, d, act, s_h, nullptr, wm, wn, lane);
        gemm(bw + (size_t)(9 + 32*b + 16)*512, 16, actu, arow0, arow1, d, 1);
        epilogue(2, blkb2 + b*256, d, act, s_h, nullptr, wm, wn, lane);
    }

    gemm(bw + (size_t)137*512, 16, actu, arow0, arow1, d, 1);

    __syncthreads();                       // Wout GEMM done reading act
    for (int i = tid; i < 128*144; i += 512) {
        int r = i / 144, c = i - r*144;
        act[r*AP + c] = __float2half_rn(c < SD ? st[r*SD + c] : 0.f);
    }
    __syncthreads();

    gemm(bw + (size_t)153*512, 9, actu, arow0, arow1, d, 0);
    epilogue(3, g_bias2, d, act, s_h, out + row0*SD, wm, wn, lane);
}

extern "C" void kernel_launch(void* const* d_in, const int* in_sizes, int n_in,
                              void* d_out, int out_size) {
    const float* t        = (const float*)d_in[0];
    const float* state    = (const float*)d_in[1];
    const float* W0       = (const float*)d_in[2];
    const float* b0       = (const float*)d_in[3];
    const float* blkW1    = (const float*)d_in[4];
    const float* blkb1    = (const float*)d_in[5];
    const float* blkW2    = (const float*)d_in[6];
    const float* blkb2    = (const float*)d_in[7];
    const float* Wout     = (const float*)d_in[8];
    const float* bout     = (const float*)d_in[9];
    const float* lm_in_w  = (const float*)d_in[10];
    const float* lm_in_b  = (const float*)d_in[11];
    const float* lm_out_w = (const float*)d_in[12];
    const float* lm_out_b = (const float*)d_in[13];
    const float* ta_in_w  = (const float*)d_in[14];
    const float* ta_in_b  = (const float*)d_in[15];
    const float* ta_out_w = (const float*)d_in[16];
    const float* ta_out_b = (const float*)d_in[17];
    float* out = (float*)d_out;

    cudaFuncSetAttribute(ode_mma_full, cudaFuncAttributeMaxDynamicSharedMemorySize, SMEM_SZ);
    prep1<<<1, 256>>>(t, W0, b0, bout, lm_in_w, lm_in_b, lm_out_w, lm_out_b,
                      ta_in_b, ta_out_w, ta_out_b);
    prepW<<<77, 256>>>(ta_in_w, ta_out_w, lm_in_w, lm_out_w);
    prepW2<<<2592, 256>>>(W0, blkW1, blkW2, Wout);
    ode_mma_full<<<1024, 512, SMEM_SZ>>>(state, blkb1, blkb2, out);
}

// round 11
// speedup vs baseline: 1.4329x; 1.4329x over previous
#include <cuda_runtime.h>
#include <cuda_fp16.h>
#include <cstdint>

#define SD   137
#define HIDN 256
#define AP   264
#define OFF_H   0                      // h fp32 [128][256] = 131072 B
#define OFF_ACT 131072                 // act fp16 [128][264] = 67584 B
#define SMEM_SZ (OFF_ACT + 67584)      // 198656

#define NCHUNK 162
__device__ float g_b0p[HIDN];
__device__ float g_Waug[144*136];
__device__ float g_bias2[144];
// per-chunk fragment-ordered weights: [chunk][wn(4)][p(4)][lane(32)][8 halves]
__device__ __align__(16) __half g_Wf[NCHUNK*4096];

__device__ __forceinline__ float tanh_fast(float x){
    float e = __expf(2.f*x); return 1.f - __fdividef(2.f, e + 1.f);
}
__device__ __forceinline__ uint32_t s2u(const void* p){
    uint32_t a;
    asm("{ .reg .u64 t; cvta.to.shared.u64 t, %1; cvt.u32.u64 %0, t; }" : "=r"(a) : "l"(p));
    return a;
}
#define MMA(d, a0, a1, a2, a3, b0, b1) asm volatile( \
    "mma.sync.aligned.m16n8k16.row.col.f32.f16.f16.f32 " \
    "{%0,%1,%2,%3}, {%4,%5,%6,%7}, {%8,%9}, {%0,%1,%2,%3};" \
    : "+f"((d)[0]), "+f"((d)[1]), "+f"((d)[2]), "+f"((d)[3]) \
    : "r"(a0), "r"(a1), "r"(a2), "r"(a3), "r"(b0), "r"(b1))
#define LDM4(r, addr) asm volatile( \
    "ldmatrix.sync.aligned.m8n8.x4.shared.b16 {%0,%1,%2,%3}, [%4];" \
    : "=r"((r)[0]), "=r"((r)[1]), "=r"((r)[2]), "=r"((r)[3]) : "r"(addr))
#define GBAR(id) asm volatile("bar.sync %0, 128;" :: "r"(id) : "memory")

// ---------------- prep ----------------
__global__ void prep1(const float* __restrict__ t, const float* __restrict__ W0,
                      const float* __restrict__ b0, const float* __restrict__ bout,
                      const float* __restrict__ lm_in_w, const float* __restrict__ lm_in_b,
                      const float* __restrict__ lm_out_w, const float* __restrict__ lm_out_b,
                      const float* __restrict__ ta_in_b,
                      const float* __restrict__ ta_out_w, const float* __restrict__ ta_out_b){
    int i = threadIdx.x;
    float ang = t[0] * (2.0f * 3.14159265358979323846f / 24.0f);
    g_b0p[i] = b0[i] + sinf(ang)*W0[i*139+137] + cosf(ang)*W0[i*139+138];
    if (i < 128) {
        float a = ta_out_b[i];
        for (int k = 0; k < 128; k++) a += ta_out_w[i*128+k] * ta_in_b[256+k];
        g_bias2[i] = bout[i] + 0.1f*a;
    } else if (i < 136) {
        int j = i - 128;
        float a = lm_out_b[j];
        for (int k = 0; k < 8; k++) a += lm_out_w[j*8+k] * lm_in_b[16+k];
        g_bias2[i] = bout[i] + 0.1f*a;
    } else if (i < 144) {
        g_bias2[i] = (i == 136) ? bout[136] : 0.f;
    }
}

__global__ void prepW(const float* __restrict__ ta_in_w, const float* __restrict__ ta_out_w,
                      const float* __restrict__ lm_in_w, const float* __restrict__ lm_out_w){
    int idx = blockIdx.x*blockDim.x + threadIdx.x;
    if (idx >= 144*136) return;
    int n = idx / 136, k = idx - n*136;
    float v = 0.f;
    if (n < 128 && k < 128) {
        for (int m = 0; m < 128; m++) v += ta_out_w[n*128+m] * ta_in_w[(256+m)*128+k];
    } else if (n >= 128 && n < 136 && k >= 128) {
        for (int m = 0; m < 8; m++) v += lm_out_w[(n-128)*8+m] * lm_in_w[(16+m)*8+(k-128)];
    }
    if (n == k && n < 136) v -= 1.f;
    g_Waug[idx] = 0.1f * v;
}

// weights -> fp16 in per-lane MMA fragment order
__global__ void prepW2(const float* __restrict__ W0, const float* __restrict__ W1,
                       const float* __restrict__ W2, const float* __restrict__ Wout){
    int idx = blockIdx.x*blockDim.x + threadIdx.x;
    if (idx >= NCHUNK*4096) return;
    int c = idx >> 12, e = idx & 4095;
    int g = e >> 10, p = (e >> 8) & 3, l = (e >> 3) & 31, j = e & 7;
    int r0 = l >> 2, kk2 = (l & 3) * 2;
    int ni = 2*p + (j >> 2), jj = j & 3;
    int n = 64*g + 8*ni + r0;
    int kloc = kk2 + (jj & 1) + 8*(jj >> 1);

    const float* W; int ldw, nvalid, kmax, ci;
    if (c < 9)        { W = W0; ldw = 139; nvalid = 256; kmax = 137; ci = c; }
    else if (c < 137) { int cc = c - 9, b = cc >> 5, r = cc & 31;
                        W = (r < 16 ? W1 : W2) + b*65536; ci = r & 15;
                        ldw = 256; nvalid = 256; kmax = 256; }
    else if (c < 153) { W = Wout;   ldw = 256; nvalid = 137; kmax = 256; ci = c - 137; }
    else              { W = g_Waug; ldw = 136; nvalid = 144; kmax = 136; ci = c - 153; }
    int k = ci*16 + kloc;
    g_Wf[idx] = __float2half_rn((n < nvalid && k < kmax) ? W[n*ldw + k] : 0.f);
}

// ---------------- barrier-free GEMM with register double-buffered B ----------------
__device__ __forceinline__ void gemm(const uint4* __restrict__ bp, int nch,
    uint32_t actu, uint32_t arow0, uint32_t arow1, float (*d)[8][4], int fresh)
{
    if (fresh)
        #pragma unroll
        for (int mi = 0; mi < 2; mi++)
            #pragma unroll
            for (int ni = 0; ni < 8; ni++)
                #pragma unroll
                for (int e = 0; e < 4; e++) d[mi][ni][e] = 0.f;

    uint4 c0 = __ldg(bp), c1 = __ldg(bp + 32), c2 = __ldg(bp + 64), c3 = __ldg(bp + 96);

    #pragma unroll 1
    for (int ci = 0; ci < nch; ci++) {
        uint4 n0, n1, n2, n3;
        if (ci + 1 < nch) {
            const uint4* np = bp + (ci + 1) * 512;
            n0 = __ldg(np);      n1 = __ldg(np + 32);
            n2 = __ldg(np + 64); n3 = __ldg(np + 96);
        }
        uint32_t a0[4], a1[4];
        const uint32_t k2 = (uint32_t)(ci * 32);
        LDM4(a0, actu + arow0 + k2);
        LDM4(a1, actu + arow1 + k2);
        MMA(d[0][0], a0[0],a0[1],a0[2],a0[3], c0.x, c0.y);
        MMA(d[1][0], a1[0],a1[1],a1[2],a1[3], c0.x, c0.y);
        MMA(d[0][1], a0[0],a0[1],a0[2],a0[3], c0.z, c0.w);
        MMA(d[1][1], a1[0],a1[1],a1[2],a1[3], c0.z, c0.w);
        MMA(d[0][2], a0[0],a0[1],a0[2],a0[3], c1.x, c1.y);
        MMA(d[1][2], a1[0],a1[1],a1[2],a1[3], c1.x, c1.y);
        MMA(d[0][3], a0[0],a0[1],a0[2],a0[3], c1.z, c1.w);
        MMA(d[1][3], a1[0],a1[1],a1[2],a1[3], c1.z, c1.w);
        MMA(d[0][4], a0[0],a0[1],a0[2],a0[3], c2.x, c2.y);
        MMA(d[1][4], a1[0],a1[1],a1[2],a1[3], c2.x, c2.y);
        MMA(d[0][5], a0[0],a0[1],a0[2],a0[3], c2.z, c2.w);
        MMA(d[1][5], a1[0],a1[1],a1[2],a1[3], c2.z, c2.w);
        MMA(d[0][6], a0[0],a0[1],a0[2],a0[3], c3.x, c3.y);
        MMA(d[1][6], a1[0],a1[1],a1[2],a1[3], c3.x, c3.y);
        MMA(d[0][7], a0[0],a0[1],a0[2],a0[3], c3.z, c3.w);
        MMA(d[1][7], a1[0],a1[1],a1[2],a1[3], c3.z, c3.w);
        if (ci + 1 < nch) { c0 = n0; c1 = n1; c2 = n2; c3 = n3; }
    }
}

// mode: 0 relu->h+act, 1 tanh->act, 2 tanh(h+.)->h+act, 3 final store
// group barrier: only the 4 warps sharing wm touch rows 32wm..32wm+31
__device__ __forceinline__ void epilogue(int mode, const float* __restrict__ bias,
    float (*d)[8][4], __half* __restrict__ act, float* __restrict__ s_h,
    float* __restrict__ outp, int wm, int wn, int lane)
{
    GBAR(wm + 1);                          // wm-group done reading act rows
    const int r0 = lane >> 2, tg = lane & 3;
    #pragma unroll
    for (int mi = 0; mi < 2; mi++)
    #pragma unroll
    for (int ni = 0; ni < 8; ni++)
    #pragma unroll
    for (int e = 0; e < 4; e++) {
        int rr = 32*wm + 16*mi + r0 + (e >> 1)*8;
        int cc = 64*wn + 8*ni + tg*2 + (e & 1);
        float v = d[mi][ni][e];
        if (mode == 3) {
            if (cc < SD) outp[rr*SD + cc] = v + bias[cc];
        } else {
            float x = v + bias[cc];
            if (mode == 0)      x = fmaxf(x, 0.f);
            else if (mode == 1) x = tanh_fast(x);
            else                x = tanh_fast(s_h[rr*256 + cc] + x);
            if (mode != 1) s_h[rr*256 + cc] = x;
            act[rr*AP + cc] = __float2half_rn(x);
        }
    }
    if (mode != 3) GBAR(wm + 1);           // act rows visible to wm-group
}

// ---------------- main ----------------
extern "C" __global__ void __launch_bounds__(512, 1)
ode_mma_full(const float* __restrict__ state,
             const float* __restrict__ blkb1, const float* __restrict__ blkb2,
             float* __restrict__ out)
{
    extern __shared__ char smem[];
    float*  s_h  = (float*)(smem + OFF_H);
    __half* act  = (__half*)(smem + OFF_ACT);
    const uint32_t actu = s2u(act);
    const int tid = threadIdx.x, lane = tid & 31, wid = tid >> 5;
    const int wm = wid & 3, wn = wid >> 2;
    const size_t row0 = (size_t)blockIdx.x * 128;
    const float* st = state + row0 * SD;

    const uint32_t arow0 = (uint32_t)(((32*wm + (lane & 15))*AP + ((lane >> 4) << 3)) * 2);
    const uint32_t arow1 = arow0 + (uint32_t)(16*AP*2);
    const uint4* bw = (const uint4*)g_Wf + wn*128 + lane;

    // group-local index across the 4 warps of group wm (wn = 0..3 differ)
    const int sub = wn*32 + lane;

    // init act rows: each wm-group writes exactly its own 32 rows
    for (int i = sub; i < 32*144; i += 128) {
        int r = 32*wm + i / 144, c = i % 144;
        act[r*AP + c] = __float2half_rn(c < SD ? st[r*SD + c] : 0.f);
    }
    GBAR(wm + 1);

    float d[2][8][4];

    gemm(bw, 9, actu, arow0, arow1, d, 1);
    epilogue(0, g_b0p, d, act, s_h, nullptr, wm, wn, lane);

    for (int b = 0; b < 4; b++) {
        gemm(bw + (size_t)(9 + 32*b)*512, 16, actu, arow0, arow1, d, 1);
        epilogue(1, blkb1 + b*256, d, act, s_h, nullptr, wm, wn, lane);
        gemm(bw + (size_t)(9 + 32*b + 16)*512, 16, actu, arow0, arow1, d, 1);
        epilogue(2, blkb2 + b*256, d, act, s_h, nullptr, wm, wn, lane);
    }

    gemm(bw + (size_t)137*512, 16, actu, arow0, arow1, d, 1);

    GBAR(wm + 1);                          // Wout GEMM done reading act rows
    for (int i = sub; i < 32*144; i += 128) {
        int r = 32*wm + i / 144, c = i % 144;
        act[r*AP + c] = __float2half_rn(c < SD ? st[r*SD + c] : 0.f);
    }
    GBAR(wm + 1);

    gemm(bw + (size_t)153*512, 9, actu, arow0, arow1, d, 0);
    epilogue(3, g_bias2, d, act, s_h, out + row0*SD, wm, wn, lane);
}

extern "C" void kernel_launch(void* const* d_in, const int* in_sizes, int n_in,
                              void* d_out, int out_size) {
    const float* t        = (const float*)d_in[0];
    const float* state    = (const float*)d_in[1];
    const float* W0       = (const float*)d_in[2];
    const float* b0       = (const float*)d_in[3];
    const float* blkW1    = (const float*)d_in[4];
    const float* blkb1    = (const float*)d_in[5];
    const float* blkW2    = (const float*)d_in[6];
    const float* blkb2    = (const float*)d_in[7];
    const float* Wout     = (const float*)d_in[8];
    const float* bout     = (const float*)d_in[9];
    const float* lm_in_w  = (const float*)d_in[10];
    const float* lm_in_b  = (const float*)d_in[11];
    const float* lm_out_w = (const float*)d_in[12];
    const float* lm_out_b = (const float*)d_in[13];
    const float* ta_in_w  = (const float*)d_in[14];
    const float* ta_in_b  = (const float*)d_in[15];
    const float* ta_out_w = (const float*)d_in[16];
    const float* ta_out_b = (const float*)d_in[17];
    float* out = (float*)d_out;

    cudaFuncSetAttribute(ode_mma_full, cudaFuncAttributeMaxDynamicSharedMemorySize, SMEM_SZ);
    prep1<<<1, 256>>>(t, W0, b0, bout, lm_in_w, lm_in_b, lm_out_w, lm_out_b,
                      ta_in_b, ta_out_w, ta_out_b);
    prepW<<<77, 256>>>(ta_in_w, ta_out_w, lm_in_w, lm_out_w);
    prepW2<<<2592, 256>>>(W0, blkW1, blkW2, Wout);
    ode_mma_full<<<1024, 512, SMEM_SZ>>>(state, blkb1, blkb2, out);
}

// round 12
// speedup vs baseline: 1.5158x; 1.0579x over previous
#include <cuda_runtime.h>
#include <cuda_fp16.h>
#include <cstdint>

#define SD   137
#define HIDN 256
#define AP   264
#define OFF_H   0                      // h fp32 [128][256] = 131072 B
#define OFF_ACT 131072                 // act fp16 [128][264] = 67584 B
#define SMEM_SZ (OFF_ACT + 67584)      // 198656

#define NCHUNK 162
__device__ float g_b0p[HIDN];
__device__ float g_Waug[144*136];
__device__ float g_bias2[144];
// per-chunk fragment-ordered weights (+2 pad chunks for unconditional prefetch)
__device__ __align__(16) __half g_Wf[(NCHUNK+2)*4096];

__device__ __forceinline__ float tanh_fast(float x){
    float e = __expf(2.f*x); return 1.f - __fdividef(2.f, e + 1.f);
}
__device__ __forceinline__ uint32_t s2u(const void* p){
    uint32_t a;
    asm("{ .reg .u64 t; cvta.to.shared.u64 t, %1; cvt.u32.u64 %0, t; }" : "=r"(a) : "l"(p));
    return a;
}
#define MMA(d, a0, a1, a2, a3, b0, b1) asm volatile( \
    "mma.sync.aligned.m16n8k16.row.col.f32.f16.f16.f32 " \
    "{%0,%1,%2,%3}, {%4,%5,%6,%7}, {%8,%9}, {%0,%1,%2,%3};" \
    : "+f"((d)[0]), "+f"((d)[1]), "+f"((d)[2]), "+f"((d)[3]) \
    : "r"(a0), "r"(a1), "r"(a2), "r"(a3), "r"(b0), "r"(b1))
#define LDM4(r, addr) asm volatile( \
    "ldmatrix.sync.aligned.m8n8.x4.shared.b16 {%0,%1,%2,%3}, [%4];" \
    : "=r"((r)[0]), "=r"((r)[1]), "=r"((r)[2]), "=r"((r)[3]) : "r"(addr))
#define GBAR(id) asm volatile("bar.sync %0, 128;" :: "r"(id) : "memory")
#define PF_L1(p) asm volatile("prefetch.global.L1 [%0];" :: "l"(p))

// ---------------- prep ----------------
__global__ void prep1(const float* __restrict__ t, const float* __restrict__ W0,
                      const float* __restrict__ b0, const float* __restrict__ bout,
                      const float* __restrict__ lm_in_w, const float* __restrict__ lm_in_b,
                      const float* __restrict__ lm_out_w, const float* __restrict__ lm_out_b,
                      const float* __restrict__ ta_in_b,
                      const float* __restrict__ ta_out_w, const float* __restrict__ ta_out_b){
    int i = threadIdx.x;
    float ang = t[0] * (2.0f * 3.14159265358979323846f / 24.0f);
    g_b0p[i] = b0[i] + sinf(ang)*W0[i*139+137] + cosf(ang)*W0[i*139+138];
    if (i < 128) {
        float a = ta_out_b[i];
        for (int k = 0; k < 128; k++) a += ta_out_w[i*128+k] * ta_in_b[256+k];
        g_bias2[i] = bout[i] + 0.1f*a;
    } else if (i < 136) {
        int j = i - 128;
        float a = lm_out_b[j];
        for (int k = 0; k < 8; k++) a += lm_out_w[j*8+k] * lm_in_b[16+k];
        g_bias2[i] = bout[i] + 0.1f*a;
    } else if (i < 144) {
        g_bias2[i] = (i == 136) ? bout[136] : 0.f;
    }
}

__global__ void prepW(const float* __restrict__ ta_in_w, const float* __restrict__ ta_out_w,
                      const float* __restrict__ lm_in_w, const float* __restrict__ lm_out_w){
    int idx = blockIdx.x*blockDim.x + threadIdx.x;
    if (idx >= 144*136) return;
    int n = idx / 136, k = idx - n*136;
    float v = 0.f;
    if (n < 128 && k < 128) {
        for (int m = 0; m < 128; m++) v += ta_out_w[n*128+m] * ta_in_w[(256+m)*128+k];
    } else if (n >= 128 && n < 136 && k >= 128) {
        for (int m = 0; m < 8; m++) v += lm_out_w[(n-128)*8+m] * lm_in_w[(16+m)*8+(k-128)];
    }
    if (n == k && n < 136) v -= 1.f;
    g_Waug[idx] = 0.1f * v;
}

// weights -> fp16 in per-lane MMA fragment order (pad chunks zeroed)
__global__ void prepW2(const float* __restrict__ W0, const float* __restrict__ W1,
                       const float* __restrict__ W2, const float* __restrict__ Wout){
    int idx = blockIdx.x*blockDim.x + threadIdx.x;
    if (idx >= (NCHUNK+2)*4096) return;
    int c = idx >> 12, e = idx & 4095;
    if (c >= NCHUNK) { g_Wf[idx] = __float2half_rn(0.f); return; }
    int g = e >> 10, p = (e >> 8) & 3, l = (e >> 3) & 31, j = e & 7;
    int r0 = l >> 2, kk2 = (l & 3) * 2;
    int ni = 2*p + (j >> 2), jj = j & 3;
    int n = 64*g + 8*ni + r0;
    int kloc = kk2 + (jj & 1) + 8*(jj >> 1);

    const float* W; int ldw, nvalid, kmax, ci;
    if (c < 9)        { W = W0; ldw = 139; nvalid = 256; kmax = 137; ci = c; }
    else if (c < 137) { int cc = c - 9, b = cc >> 5, r = cc & 31;
                        W = (r < 16 ? W1 : W2) + b*65536; ci = r & 15;
                        ldw = 256; nvalid = 256; kmax = 256; }
    else if (c < 153) { W = Wout;   ldw = 256; nvalid = 137; kmax = 256; ci = c - 137; }
    else              { W = g_Waug; ldw = 136; nvalid = 144; kmax = 136; ci = c - 153; }
    int k = ci*16 + kloc;
    g_Wf[idx] = __float2half_rn((n < nvalid && k < kmax) ? W[n*ldw + k] : 0.f);
}

// ---------------- GEMM: reg double-buffer B + L1 prefetch distance 2 ----------------
__device__ __forceinline__ void gemm(const uint4* __restrict__ bp, int nch,
    uint32_t actu, uint32_t arow0, uint32_t arow1, float (*d)[8][4], int fresh)
{
    if (fresh)
        #pragma unroll
        for (int mi = 0; mi < 2; mi++)
            #pragma unroll
            for (int ni = 0; ni < 8; ni++)
                #pragma unroll
                for (int e = 0; e < 4; e++) d[mi][ni][e] = 0.f;

    const uint4* p = bp;
    uint4 c0 = __ldg(p), c1 = __ldg(p + 32), c2 = __ldg(p + 64), c3 = __ldg(p + 96);
    PF_L1(p + 512); PF_L1(p + 544); PF_L1(p + 576); PF_L1(p + 608);
    uint32_t k2 = 0;

    #pragma unroll 1
    for (int ci = 0; ci < nch; ci++) {
        PF_L1(p + 1024); PF_L1(p + 1056); PF_L1(p + 1088); PF_L1(p + 1120);
        uint4 n0 = __ldg(p + 512), n1 = __ldg(p + 544),
              n2 = __ldg(p + 576), n3 = __ldg(p + 608);
        uint32_t a0[4], a1[4];
        LDM4(a0, actu + arow0 + k2);
        LDM4(a1, actu + arow1 + k2);
        MMA(d[0][0], a0[0],a0[1],a0[2],a0[3], c0.x, c0.y);
        MMA(d[1][0], a1[0],a1[1],a1[2],a1[3], c0.x, c0.y);
        MMA(d[0][1], a0[0],a0[1],a0[2],a0[3], c0.z, c0.w);
        MMA(d[1][1], a1[0],a1[1],a1[2],a1[3], c0.z, c0.w);
        MMA(d[0][2], a0[0],a0[1],a0[2],a0[3], c1.x, c1.y);
        MMA(d[1][2], a1[0],a1[1],a1[2],a1[3], c1.x, c1.y);
        MMA(d[0][3], a0[0],a0[1],a0[2],a0[3], c1.z, c1.w);
        MMA(d[1][3], a1[0],a1[1],a1[2],a1[3], c1.z, c1.w);
        MMA(d[0][4], a0[0],a0[1],a0[2],a0[3], c2.x, c2.y);
        MMA(d[1][4], a1[0],a1[1],a1[2],a1[3], c2.x, c2.y);
        MMA(d[0][5], a0[0],a0[1],a0[2],a0[3], c2.z, c2.w);
        MMA(d[1][5], a1[0],a1[1],a1[2],a1[3], c2.z, c2.w);
        MMA(d[0][6], a0[0],a0[1],a0[2],a0[3], c3.x, c3.y);
        MMA(d[1][6], a1[0],a1[1],a1[2],a1[3], c3.x, c3.y);
        MMA(d[0][7], a0[0],a0[1],a0[2],a0[3], c3.z, c3.w);
        MMA(d[1][7], a1[0],a1[1],a1[2],a1[3], c3.z, c3.w);
        c0 = n0; c1 = n1; c2 = n2; c3 = n3;
        p += 512; k2 += 32;
    }
}

// mode: 0 relu->h+act, 1 tanh->act, 2 tanh(h+.)->h+act, 3 final store
__device__ __forceinline__ void epilogue(int mode, const float* __restrict__ bias,
    float (*d)[8][4], __half* __restrict__ act, float* __restrict__ s_h,
    float* __restrict__ outp, int wm, int wn, int lane)
{
    GBAR(wm + 1);                          // wm-group done reading act rows
    const int r0 = lane >> 2, tg = lane & 3;
    #pragma unroll
    for (int mi = 0; mi < 2; mi++)
    #pragma unroll
    for (int ni = 0; ni < 8; ni++) {
        const int cc = 64*wn + 8*ni + tg*2;
        const float b0v = bias[cc], b1v = bias[cc + 1];
        #pragma unroll
        for (int half = 0; half < 2; half++) {   // e pair (2h, 2h+1): same row
            int rr = 32*wm + 16*mi + r0 + half*8;
            float x0 = d[mi][ni][2*half]     + b0v;
            float x1 = d[mi][ni][2*half + 1] + b1v;
            if (mode == 3) {
                if (cc < SD)     outp[rr*SD + cc]     = x0;
                if (cc + 1 < SD) outp[rr*SD + cc + 1] = x1;
            } else {
                if (mode == 0) { x0 = fmaxf(x0, 0.f); x1 = fmaxf(x1, 0.f); }
                else if (mode == 1) { x0 = tanh_fast(x0); x1 = tanh_fast(x1); }
                else {
                    float2 hv = *(const float2*)(s_h + rr*256 + cc);
                    x0 = tanh_fast(hv.x + x0); x1 = tanh_fast(hv.y + x1);
                }
                if (mode != 1) *(float2*)(s_h + rr*256 + cc) = make_float2(x0, x1);
                *(__half2*)(act + rr*AP + cc) = __halves2half2(__float2half_rn(x0),
                                                               __float2half_rn(x1));
            }
        }
    }
    if (mode != 3) GBAR(wm + 1);           // act rows visible to wm-group
}

// ---------------- main ----------------
extern "C" __global__ void __launch_bounds__(512, 1)
ode_mma_full(const float* __restrict__ state,
             const float* __restrict__ blkb1, const float* __restrict__ blkb2,
             float* __restrict__ out)
{
    extern __shared__ char smem[];
    float*  s_h  = (float*)(smem + OFF_H);
    __half* act  = (__half*)(smem + OFF_ACT);
    const uint32_t actu = s2u(act);
    const int tid = threadIdx.x, lane = tid & 31, wid = tid >> 5;
    const int wm = wid & 3, wn = wid >> 2;
    const size_t row0 = (size_t)blockIdx.x * 128;
    const float* st = state + row0 * SD;

    const uint32_t arow0 = (uint32_t)(((32*wm + (lane & 15))*AP + ((lane >> 4) << 3)) * 2);
    const uint32_t arow1 = arow0 + (uint32_t)(16*AP*2);
    const uint4* bw = (const uint4*)g_Wf + wn*128 + lane;

    const int sub = wn*32 + lane;          // group-local index (wn differs in group)

    for (int i = sub; i < 32*144; i += 128) {
        int r = 32*wm + i / 144, c = i % 144;
        act[r*AP + c] = __float2half_rn(c < SD ? st[r*SD + c] : 0.f);
    }
    GBAR(wm + 1);

    float d[2][8][4];

    gemm(bw, 9, actu, arow0, arow1, d, 1);
    epilogue(0, g_b0p, d, act, s_h, nullptr, wm, wn, lane);

    for (int b = 0; b < 4; b++) {
        gemm(bw + (size_t)(9 + 32*b)*512, 16, actu, arow0, arow1, d, 1);
        epilogue(1, blkb1 + b*256, d, act, s_h, nullptr, wm, wn, lane);
        gemm(bw + (size_t)(9 + 32*b + 16)*512, 16, actu, arow0, arow1, d, 1);
        epilogue(2, blkb2 + b*256, d, act, s_h, nullptr, wm, wn, lane);
    }

    gemm(bw + (size_t)137*512, 16, actu, arow0, arow1, d, 1);

    GBAR(wm + 1);                          // Wout GEMM done reading act rows
    for (int i = sub; i < 32*144; i += 128) {
        int r = 32*wm + i / 144, c = i % 144;
        act[r*AP + c] = __float2half_rn(c < SD ? st[r*SD + c] : 0.f);
    }
    GBAR(wm + 1);

    gemm(bw + (size_t)153*512, 9, actu, arow0, arow1, d, 0);
    epilogue(3, g_bias2, d, act, s_h, out + row0*SD, wm, wn, lane);
}

extern "C" void kernel_launch(void* const* d_in, const int* in_sizes, int n_in,
                              void* d_out, int out_size) {
    const float* t        = (const float*)d_in[0];
    const float* state    = (const float*)d_in[1];
    const float* W0       = (const float*)d_in[2];
    const float* b0       = (const float*)d_in[3];
    const float* blkW1    = (const float*)d_in[4];
    const float* blkb1    = (const float*)d_in[5];
    const float* blkW2    = (const float*)d_in[6];
    const float* blkb2    = (const float*)d_in[7];
    const float* Wout     = (const float*)d_in[8];
    const float* bout     = (const float*)d_in[9];
    const float* lm_in_w  = (const float*)d_in[10];
    const float* lm_in_b  = (const float*)d_in[11];
    const float* lm_out_w = (const float*)d_in[12];
    const float* lm_out_b = (const float*)d_in[13];
    const float* ta_in_w  = (const float*)d_in[14];
    const float* ta_in_b  = (const float*)d_in[15];
    const float* ta_out_w = (const float*)d_in[16];
    const float* ta_out_b = (const float*)d_in[17];
    float* out = (float*)d_out;

    cudaFuncSetAttribute(ode_mma_full, cudaFuncAttributeMaxDynamicSharedMemorySize, SMEM_SZ);
    prep1<<<1, 256>>>(t, W0, b0, bout, lm_in_w, lm_in_b, lm_out_w, lm_out_b,
                      ta_in_b, ta_out_w, ta_out_b);
    prepW<<<77, 256>>>(ta_in_w, ta_out_w, lm_in_w, lm_out_w);
    prepW2<<<2624, 256>>>(W0, blkW1, blkW2, Wout);
    ode_mma_full<<<1024, 512, SMEM_SZ>>>(state, blkb1, blkb2, out);
}

// round 13
// speedup vs baseline: 1.6148x; 1.0653x over previous
#include <cuda_runtime.h>
#include <cuda_fp16.h>
#include <cstdint>

#define SD   137
#define HIDN 256
#define AP   264
#define MROWS 64
#define OFF_H   0                      // h fp32 [64][256] = 65536 B
#define OFF_ACT 65536                  // act fp16 [64][264] = 33792 B
#define SMEM_SZ (OFF_ACT + 33792)      // 99328 -> 2 CTAs/SM

#define NCHUNK 162
__device__ float g_b0p[HIDN];
__device__ float g_Waug[144*136];
__device__ float g_bias2[144];
// per-chunk fragment-ordered weights (+2 pad chunks for unconditional prefetch)
__device__ __align__(16) __half g_Wf[(NCHUNK+2)*4096];

__device__ __forceinline__ float tanh_fast(float x){
    float e = __expf(2.f*x); return 1.f - __fdividef(2.f, e + 1.f);
}
__device__ __forceinline__ uint32_t s2u(const void* p){
    uint32_t a;
    asm("{ .reg .u64 t; cvta.to.shared.u64 t, %1; cvt.u32.u64 %0, t; }" : "=r"(a) : "l"(p));
    return a;
}
#define MMA(d, a0, a1, a2, a3, b0, b1) asm volatile( \
    "mma.sync.aligned.m16n8k16.row.col.f32.f16.f16.f32 " \
    "{%0,%1,%2,%3}, {%4,%5,%6,%7}, {%8,%9}, {%0,%1,%2,%3};" \
    : "+f"((d)[0]), "+f"((d)[1]), "+f"((d)[2]), "+f"((d)[3]) \
    : "r"(a0), "r"(a1), "r"(a2), "r"(a3), "r"(b0), "r"(b1))
#define LDM4(r, addr) asm volatile( \
    "ldmatrix.sync.aligned.m8n8.x4.shared.b16 {%0,%1,%2,%3}, [%4];" \
    : "=r"((r)[0]), "=r"((r)[1]), "=r"((r)[2]), "=r"((r)[3]) : "r"(addr))
#define GBAR(id) asm volatile("bar.sync %0, 128;" :: "r"(id) : "memory")
#define PF_L1(p) asm volatile("prefetch.global.L1 [%0];" :: "l"(p))

// ---------------- prep ----------------
__global__ void prep1(const float* __restrict__ t, const float* __restrict__ W0,
                      const float* __restrict__ b0, const float* __restrict__ bout,
                      const float* __restrict__ lm_in_w, const float* __restrict__ lm_in_b,
                      const float* __restrict__ lm_out_w, const float* __restrict__ lm_out_b,
                      const float* __restrict__ ta_in_b,
                      const float* __restrict__ ta_out_w, const float* __restrict__ ta_out_b){
    int i = threadIdx.x;
    float ang = t[0] * (2.0f * 3.14159265358979323846f / 24.0f);
    g_b0p[i] = b0[i] + sinf(ang)*W0[i*139+137] + cosf(ang)*W0[i*139+138];
    if (i < 128) {
        float a = ta_out_b[i];
        for (int k = 0; k < 128; k++) a += ta_out_w[i*128+k] * ta_in_b[256+k];
        g_bias2[i] = bout[i] + 0.1f*a;
    } else if (i < 136) {
        int j = i - 128;
        float a = lm_out_b[j];
        for (int k = 0; k < 8; k++) a += lm_out_w[j*8+k] * lm_in_b[16+k];
        g_bias2[i] = bout[i] + 0.1f*a;
    } else if (i < 144) {
        g_bias2[i] = (i == 136) ? bout[136] : 0.f;
    }
}

__global__ void prepW(const float* __restrict__ ta_in_w, const float* __restrict__ ta_out_w,
                      const float* __restrict__ lm_in_w, const float* __restrict__ lm_out_w){
    int idx = blockIdx.x*blockDim.x + threadIdx.x;
    if (idx >= 144*136) return;
    int n = idx / 136, k = idx - n*136;
    float v = 0.f;
    if (n < 128 && k < 128) {
        for (int m = 0; m < 128; m++) v += ta_out_w[n*128+m] * ta_in_w[(256+m)*128+k];
    } else if (n >= 128 && n < 136 && k >= 128) {
        for (int m = 0; m < 8; m++) v += lm_out_w[(n-128)*8+m] * lm_in_w[(16+m)*8+(k-128)];
    }
    if (n == k && n < 136) v -= 1.f;
    g_Waug[idx] = 0.1f * v;
}

// weights -> fp16 in per-lane MMA fragment order (pad chunks zeroed)
__global__ void prepW2(const float* __restrict__ W0, const float* __restrict__ W1,
                       const float* __restrict__ W2, const float* __restrict__ Wout){
    int idx = blockIdx.x*blockDim.x + threadIdx.x;
    if (idx >= (NCHUNK+2)*4096) return;
    int c = idx >> 12, e = idx & 4095;
    if (c >= NCHUNK) { g_Wf[idx] = __float2half_rn(0.f); return; }
    int g = e >> 10, p = (e >> 8) & 3, l = (e >> 3) & 31, j = e & 7;
    int r0 = l >> 2, kk2 = (l & 3) * 2;
    int ni = 2*p + (j >> 2), jj = j & 3;
    int n = 64*g + 8*ni + r0;
    int kloc = kk2 + (jj & 1) + 8*(jj >> 1);

    const float* W; int ldw, nvalid, kmax, ci;
    if (c < 9)        { W = W0; ldw = 139; nvalid = 256; kmax = 137; ci = c; }
    else if (c < 137) { int cc = c - 9, b = cc >> 5, r = cc & 31;
                        W = (r < 16 ? W1 : W2) + b*65536; ci = r & 15;
                        ldw = 256; nvalid = 256; kmax = 256; }
    else if (c < 153) { W = Wout;   ldw = 256; nvalid = 137; kmax = 256; ci = c - 137; }
    else              { W = g_Waug; ldw = 136; nvalid = 144; kmax = 136; ci = c - 153; }
    int k = ci*16 + kloc;
    g_Wf[idx] = __float2half_rn((n < nvalid && k < kmax) ? W[n*ldw + k] : 0.f);
}

// ---------------- GEMM: reg double-buffer B + L1 prefetch distance 2 ----------------
__device__ __forceinline__ void gemm(const uint4* __restrict__ bp, int nch,
    uint32_t actu, uint32_t arow0, uint32_t arow1, float (*d)[8][4], int fresh)
{
    if (fresh)
        #pragma unroll
        for (int mi = 0; mi < 2; mi++)
            #pragma unroll
            for (int ni = 0; ni < 8; ni++)
                #pragma unroll
                for (int e = 0; e < 4; e++) d[mi][ni][e] = 0.f;

    const uint4* p = bp;
    uint4 c0 = __ldg(p), c1 = __ldg(p + 32), c2 = __ldg(p + 64), c3 = __ldg(p + 96);
    PF_L1(p + 512); PF_L1(p + 544); PF_L1(p + 576); PF_L1(p + 608);
    uint32_t k2 = 0;

    #pragma unroll 1
    for (int ci = 0; ci < nch; ci++) {
        PF_L1(p + 1024); PF_L1(p + 1056); PF_L1(p + 1088); PF_L1(p + 1120);
        uint4 n0 = __ldg(p + 512), n1 = __ldg(p + 544),
              n2 = __ldg(p + 576), n3 = __ldg(p + 608);
        uint32_t a0[4], a1[4];
        LDM4(a0, actu + arow0 + k2);
        LDM4(a1, actu + arow1 + k2);
        MMA(d[0][0], a0[0],a0[1],a0[2],a0[3], c0.x, c0.y);
        MMA(d[1][0], a1[0],a1[1],a1[2],a1[3], c0.x, c0.y);
        MMA(d[0][1], a0[0],a0[1],a0[2],a0[3], c0.z, c0.w);
        MMA(d[1][1], a1[0],a1[1],a1[2],a1[3], c0.z, c0.w);
        MMA(d[0][2], a0[0],a0[1],a0[2],a0[3], c1.x, c1.y);
        MMA(d[1][2], a1[0],a1[1],a1[2],a1[3], c1.x, c1.y);
        MMA(d[0][3], a0[0],a0[1],a0[2],a0[3], c1.z, c1.w);
        MMA(d[1][3], a1[0],a1[1],a1[2],a1[3], c1.z, c1.w);
        MMA(d[0][4], a0[0],a0[1],a0[2],a0[3], c2.x, c2.y);
        MMA(d[1][4], a1[0],a1[1],a1[2],a1[3], c2.x, c2.y);
        MMA(d[0][5], a0[0],a0[1],a0[2],a0[3], c2.z, c2.w);
        MMA(d[1][5], a1[0],a1[1],a1[2],a1[3], c2.z, c2.w);
        MMA(d[0][6], a0[0],a0[1],a0[2],a0[3], c3.x, c3.y);
        MMA(d[1][6], a1[0],a1[1],a1[2],a1[3], c3.x, c3.y);
        MMA(d[0][7], a0[0],a0[1],a0[2],a0[3], c3.z, c3.w);
        MMA(d[1][7], a1[0],a1[1],a1[2],a1[3], c3.z, c3.w);
        c0 = n0; c1 = n1; c2 = n2; c3 = n3;
        p += 512; k2 += 32;
    }
}

// mode: 0 relu->h+act, 1 tanh->act, 2 tanh(h+.)->h+act, 3 final store
__device__ __forceinline__ void epilogue(int mode, const float* __restrict__ bias,
    float (*d)[8][4], __half* __restrict__ act, float* __restrict__ s_h,
    float* __restrict__ outp, int wm, int wn, int lane)
{
    GBAR(wm + 1);                          // wm-group done reading act rows
    const int r0 = lane >> 2, tg = lane & 3;
    #pragma unroll
    for (int mi = 0; mi < 2; mi++)
    #pragma unroll
    for (int ni = 0; ni < 8; ni++) {
        const int cc = 64*wn + 8*ni + tg*2;
        const float b0v = bias[cc], b1v = bias[cc + 1];
        #pragma unroll
        for (int half = 0; half < 2; half++) {   // e pair (2h, 2h+1): same row
            int rr = 32*wm + 16*mi + r0 + half*8;
            float x0 = d[mi][ni][2*half]     + b0v;
            float x1 = d[mi][ni][2*half + 1] + b1v;
            if (mode == 3) {
                if (cc < SD)     outp[rr*SD + cc]     = x0;
                if (cc + 1 < SD) outp[rr*SD + cc + 1] = x1;
            } else {
                if (mode == 0) { x0 = fmaxf(x0, 0.f); x1 = fmaxf(x1, 0.f); }
                else if (mode == 1) { x0 = tanh_fast(x0); x1 = tanh_fast(x1); }
                else {
                    float2 hv = *(const float2*)(s_h + rr*256 + cc);
                    x0 = tanh_fast(hv.x + x0); x1 = tanh_fast(hv.y + x1);
                }
                if (mode != 1) *(float2*)(s_h + rr*256 + cc) = make_float2(x0, x1);
                *(__half2*)(act + rr*AP + cc) = __halves2half2(__float2half_rn(x0),
                                                               __float2half_rn(x1));
            }
        }
    }
    if (mode != 3) GBAR(wm + 1);           // act rows visible to wm-group
}

// ---------------- main: 64 rows/CTA, 256 threads, 2 CTAs/SM ----------------
extern "C" __global__ void __launch_bounds__(256, 2)
ode_mma_full(const float* __restrict__ state,
             const float* __restrict__ blkb1, const float* __restrict__ blkb2,
             float* __restrict__ out)
{
    extern __shared__ char smem[];
    float*  s_h  = (float*)(smem + OFF_H);
    __half* act  = (__half*)(smem + OFF_ACT);
    const uint32_t actu = s2u(act);
    const int tid = threadIdx.x, lane = tid & 31, wid = tid >> 5;
    const int wm = wid & 1, wn = wid >> 1;   // 2 (M) x 4 (N) warp grid
    const size_t row0 = (size_t)blockIdx.x * MROWS;
    const float* st = state + row0 * SD;

    const uint32_t arow0 = (uint32_t)(((32*wm + (lane & 15))*AP + ((lane >> 4) << 3)) * 2);
    const uint32_t arow1 = arow0 + (uint32_t)(16*AP*2);
    const uint4* bw = (const uint4*)g_Wf + wn*128 + lane;

    const int sub = wn*32 + lane;          // group-local index (wn differs in group)

    for (int i = sub; i < 32*144; i += 128) {
        int r = 32*wm + i / 144, c = i % 144;
        act[r*AP + c] = __float2half_rn(c < SD ? st[r*SD + c] : 0.f);
    }
    GBAR(wm + 1);

    float d[2][8][4];

    gemm(bw, 9, actu, arow0, arow1, d, 1);
    epilogue(0, g_b0p, d, act, s_h, nullptr, wm, wn, lane);

    for (int b = 0; b < 4; b++) {
        gemm(bw + (size_t)(9 + 32*b)*512, 16, actu, arow0, arow1, d, 1);
        epilogue(1, blkb1 + b*256, d, act, s_h, nullptr, wm, wn, lane);
        gemm(bw + (size_t)(9 + 32*b + 16)*512, 16, actu, arow0, arow1, d, 1);
        epilogue(2, blkb2 + b*256, d, act, s_h, nullptr, wm, wn, lane);
    }

    gemm(bw + (size_t)137*512, 16, actu, arow0, arow1, d, 1);

    GBAR(wm + 1);                          // Wout GEMM done reading act rows
    for (int i = sub; i < 32*144; i += 128) {
        int r = 32*wm + i / 144, c = i % 144;
        act[r*AP + c] = __float2half_rn(c < SD ? st[r*SD + c] : 0.f);
    }
    GBAR(wm + 1);

    gemm(bw + (size_t)153*512, 9, actu, arow0, arow1, d, 0);
    epilogue(3, g_bias2, d, act, s_h, out + row0*SD, wm, wn, lane);
}

extern "C" void kernel_launch(void* const* d_in, const int* in_sizes, int n_in,
                              void* d_out, int out_size) {
    const float* t        = (const float*)d_in[0];
    const float* state    = (const float*)d_in[1];
    const float* W0       = (const float*)d_in[2];
    const float* b0       = (const float*)d_in[3];
    const float* blkW1    = (const float*)d_in[4];
    const float* blkb1    = (const float*)d_in[5];
    const float* blkW2    = (const float*)d_in[6];
    const float* blkb2    = (const float*)d_in[7];
    const float* Wout     = (const float*)d_in[8];
    const float* bout     = (const float*)d_in[9];
    const float* lm_in_w  = (const float*)d_in[10];
    const float* lm_in_b  = (const float*)d_in[11];
    const float* lm_out_w = (const float*)d_in[12];
    const float* lm_out_b = (const float*)d_in[13];
    const float* ta_in_w  = (const float*)d_in[14];
    const float* ta_in_b  = (const float*)d_in[15];
    const float* ta_out_w = (const float*)d_in[16];
    const float* ta_out_b = (const float*)d_in[17];
    float* out = (float*)d_out;

    cudaFuncSetAttribute(ode_mma_full, cudaFuncAttributeMaxDynamicSharedMemorySize, SMEM_SZ);
    prep1<<<1, 256>>>(t, W0, b0, bout, lm_in_w, lm_in_b, lm_out_w, lm_out_b,
                      ta_in_b, ta_out_w, ta_out_b);
    prepW<<<77, 256>>>(ta_in_w, ta_out_w, lm_in_w, lm_out_w);
    prepW2<<<2624, 256>>>(W0, blkW1, blkW2, Wout);
    ode_mma_full<<<131072 / MROWS, 256, SMEM_SZ>>>(state, blkb1, blkb2, out);
}

// round 14
// speedup vs baseline: 1.6361x; 1.0132x over previous
#include <cuda_runtime.h>
#include <cuda_fp16.h>
#include <cstdint>

#define SD   137
#define HIDN 256
#define AP   264
#define MROWS 64
#define OFF_H   0                      // s_h per-warp frag layout, 65536 B
#define OFF_ACT 65536                  // act fp16 [64][264] = 33792 B
#define SMEM_SZ (OFF_ACT + 33792)      // 99328 -> 2 CTAs/SM

#define NCHUNK 162
__device__ float g_b0p[HIDN];
__device__ float g_Waug[144*136];
__device__ float g_bias2[144];
__device__ __align__(16) __half g_Wf[(NCHUNK+2)*4096];

__device__ __forceinline__ float tanh_fast(float x){
    float e = __expf(2.f*x); return 1.f - __fdividef(2.f, e + 1.f);
}
__device__ __forceinline__ uint32_t s2u(const void* p){
    uint32_t a;
    asm("{ .reg .u64 t; cvta.to.shared.u64 t, %1; cvt.u32.u64 %0, t; }" : "=r"(a) : "l"(p));
    return a;
}
#define MMA(d, a0, a1, a2, a3, b0, b1) asm volatile( \
    "mma.sync.aligned.m16n8k16.row.col.f32.f16.f16.f32 " \
    "{%0,%1,%2,%3}, {%4,%5,%6,%7}, {%8,%9}, {%0,%1,%2,%3};" \
    : "+f"((d)[0]), "+f"((d)[1]), "+f"((d)[2]), "+f"((d)[3]) \
    : "r"(a0), "r"(a1), "r"(a2), "r"(a3), "r"(b0), "r"(b1))
#define LDM4(r, addr) asm volatile( \
    "ldmatrix.sync.aligned.m8n8.x4.shared.b16 {%0,%1,%2,%3}, [%4];" \
    : "=r"((r)[0]), "=r"((r)[1]), "=r"((r)[2]), "=r"((r)[3]) : "r"(addr))
#define GBAR(id) asm volatile("bar.sync %0, 128;" :: "r"(id) : "memory")
#define PF_L1(p) asm volatile("prefetch.global.L1 [%0];" :: "l"(p))

// 16 MMAs of one chunk against B quad (q0..q3)
#define MMA16(d, a0, a1, q0, q1, q2, q3) do { \
    MMA(d[0][0], a0[0],a0[1],a0[2],a0[3], q0.x, q0.y); \
    MMA(d[1][0], a1[0],a1[1],a1[2],a1[3], q0.x, q0.y); \
    MMA(d[0][1], a0[0],a0[1],a0[2],a0[3], q0.z, q0.w); \
    MMA(d[1][1], a1[0],a1[1],a1[2],a1[3], q0.z, q0.w); \
    MMA(d[0][2], a0[0],a0[1],a0[2],a0[3], q1.x, q1.y); \
    MMA(d[1][2], a1[0],a1[1],a1[2],a1[3], q1.x, q1.y); \
    MMA(d[0][3], a0[0],a0[1],a0[2],a0[3], q1.z, q1.w); \
    MMA(d[1][3], a1[0],a1[1],a1[2],a1[3], q1.z, q1.w); \
    MMA(d[0][4], a0[0],a0[1],a0[2],a0[3], q2.x, q2.y); \
    MMA(d[1][4], a1[0],a1[1],a1[2],a1[3], q2.x, q2.y); \
    MMA(d[0][5], a0[0],a0[1],a0[2],a0[3], q2.z, q2.w); \
    MMA(d[1][5], a1[0],a1[1],a1[2],a1[3], q2.z, q2.w); \
    MMA(d[0][6], a0[0],a0[1],a0[2],a0[3], q3.x, q3.y); \
    MMA(d[1][6], a1[0],a1[1],a1[2],a1[3], q3.x, q3.y); \
    MMA(d[0][7], a0[0],a0[1],a0[2],a0[3], q3.z, q3.w); \
    MMA(d[1][7], a1[0],a1[1],a1[2],a1[3], q3.z, q3.w); \
} while(0)

// ---------------- prep ----------------
__global__ void prep1(const float* __restrict__ t, const float* __restrict__ W0,
                      const float* __restrict__ b0, const float* __restrict__ bout,
                      const float* __restrict__ lm_in_w, const float* __restrict__ lm_in_b,
                      const float* __restrict__ lm_out_w, const float* __restrict__ lm_out_b,
                      const float* __restrict__ ta_in_b,
                      const float* __restrict__ ta_out_w, const float* __restrict__ ta_out_b){
    int i = threadIdx.x;
    float ang = t[0] * (2.0f * 3.14159265358979323846f / 24.0f);
    g_b0p[i] = b0[i] + sinf(ang)*W0[i*139+137] + cosf(ang)*W0[i*139+138];
    if (i < 128) {
        float a = ta_out_b[i];
        for (int k = 0; k < 128; k++) a += ta_out_w[i*128+k] * ta_in_b[256+k];
        g_bias2[i] = bout[i] + 0.1f*a;
    } else if (i < 136) {
        int j = i - 128;
        float a = lm_out_b[j];
        for (int k = 0; k < 8; k++) a += lm_out_w[j*8+k] * lm_in_b[16+k];
        g_bias2[i] = bout[i] + 0.1f*a;
    } else if (i < 144) {
        g_bias2[i] = (i == 136) ? bout[136] : 0.f;
    }
}

__global__ void prepW(const float* __restrict__ ta_in_w, const float* __restrict__ ta_out_w,
                      const float* __restrict__ lm_in_w, const float* __restrict__ lm_out_w){
    int idx = blockIdx.x*blockDim.x + threadIdx.x;
    if (idx >= 144*136) return;
    int n = idx / 136, k = idx - n*136;
    float v = 0.f;
    if (n < 128 && k < 128) {
        for (int m = 0; m < 128; m++) v += ta_out_w[n*128+m] * ta_in_w[(256+m)*128+k];
    } else if (n >= 128 && n < 136 && k >= 128) {
        for (int m = 0; m < 8; m++) v += lm_out_w[(n-128)*8+m] * lm_in_w[(16+m)*8+(k-128)];
    }
    if (n == k && n < 136) v -= 1.f;
    g_Waug[idx] = 0.1f * v;
}

__global__ void prepW2(const float* __restrict__ W0, const float* __restrict__ W1,
                       const float* __restrict__ W2, const float* __restrict__ Wout){
    int idx = blockIdx.x*blockDim.x + threadIdx.x;
    if (idx >= (NCHUNK+2)*4096) return;
    int c = idx >> 12, e = idx & 4095;
    if (c >= NCHUNK) { g_Wf[idx] = __float2half_rn(0.f); return; }
    int g = e >> 10, p = (e >> 8) & 3, l = (e >> 3) & 31, j = e & 7;
    int r0 = l >> 2, kk2 = (l & 3) * 2;
    int ni = 2*p + (j >> 2), jj = j & 3;
    int n = 64*g + 8*ni + r0;
    int kloc = kk2 + (jj & 1) + 8*(jj >> 1);

    const float* W; int ldw, nvalid, kmax, ci;
    if (c < 9)        { W = W0; ldw = 139; nvalid = 256; kmax = 137; ci = c; }
    else if (c < 137) { int cc = c - 9, b = cc >> 5, r = cc & 31;
                        W = (r < 16 ? W1 : W2) + b*65536; ci = r & 15;
                        ldw = 256; nvalid = 256; kmax = 256; }
    else if (c < 153) { W = Wout;   ldw = 256; nvalid = 137; kmax = 256; ci = c - 137; }
    else              { W = g_Waug; ldw = 136; nvalid = 144; kmax = 136; ci = c - 153; }
    int k = ci*16 + kloc;
    g_Wf[idx] = __float2half_rn((n < nvalid && k < kmax) ? W[n*ldw + k] : 0.f);
}

// ---------------- GEMM: unroll-2, alternating reg buffers, PF distance 2 ----------------
template<int NCH>
__device__ __forceinline__ void gemm(const uint4* __restrict__ bp,
    uint32_t actu, uint32_t arow0, uint32_t arow1, float (*d)[8][4], int fresh)
{
    if (fresh)
        #pragma unroll
        for (int mi = 0; mi < 2; mi++)
            #pragma unroll
            for (int ni = 0; ni < 8; ni++)
                #pragma unroll
                for (int e = 0; e < 4; e++) d[mi][ni][e] = 0.f;

    const uint4* p = bp;
    uint4 c0 = __ldg(p), c1 = __ldg(p + 32), c2 = __ldg(p + 64), c3 = __ldg(p + 96);
    PF_L1(p + 512); PF_L1(p + 544); PF_L1(p + 576); PF_L1(p + 608);
    uint32_t ka0 = actu + arow0, ka1 = actu + arow1;

    #pragma unroll 1
    for (int ci = 0; ci < NCH/2; ci++) {
        // half A: consume c*, load n* (chunk 2ci+1), prefetch 2ci+2
        PF_L1(p + 1024); PF_L1(p + 1056); PF_L1(p + 1088); PF_L1(p + 1120);
        uint4 n0 = __ldg(p + 512), n1 = __ldg(p + 544),
              n2 = __ldg(p + 576), n3 = __ldg(p + 608);
        uint32_t a0[4], a1[4];
        LDM4(a0, ka0); LDM4(a1, ka1);
        MMA16(d, a0, a1, c0, c1, c2, c3);
        // half B: consume n*, load c* (chunk 2ci+2), prefetch 2ci+3
        PF_L1(p + 1536); PF_L1(p + 1568); PF_L1(p + 1600); PF_L1(p + 1632);
        c0 = __ldg(p + 1024); c1 = __ldg(p + 1056);
        c2 = __ldg(p + 1088); c3 = __ldg(p + 1120);
        LDM4(a0, ka0 + 32); LDM4(a1, ka1 + 32);
        MMA16(d, a0, a1, n0, n1, n2, n3);
        ka0 += 64; ka1 += 64;
        p += 1024;
    }
    if (NCH & 1) {
        uint32_t a0[4], a1[4];
        LDM4(a0, ka0); LDM4(a1, ka1);
        MMA16(d, a0, a1, c0, c1, c2, c3);
    }
}

// mode: 0 relu->h+act, 1 tanh->act, 2 tanh(h+.)->h+act, 3 final store
// s_h: per-warp private fragment layout, coalesced float2 [idx(32)][lane(32)]
__device__ __forceinline__ void epilogue(int mode, const float* __restrict__ bias,
    float (*d)[8][4], __half* __restrict__ act, float2* __restrict__ shw,
    float* __restrict__ outp, int wm, int wn, int lane)
{
    GBAR(wm + 1);                          // wm-group done reading act rows
    const int r0 = lane >> 2, tg = lane & 3;
    #pragma unroll
    for (int mi = 0; mi < 2; mi++)
    #pragma unroll
    for (int ni = 0; ni < 8; ni++) {
        const int cc = 64*wn + 8*ni + tg*2;
        const float b0v = bias[cc], b1v = bias[cc + 1];
        #pragma unroll
        for (int half = 0; half < 2; half++) {
            int rr = 32*wm + 16*mi + r0 + half*8;
            int idx = mi*16 + ni*2 + half;
            float x0 = d[mi][ni][2*half]     + b0v;
            float x1 = d[mi][ni][2*half + 1] + b1v;
            if (mode == 3) {
                if (cc < SD)     outp[rr*SD + cc]     = x0;
                if (cc + 1 < SD) outp[rr*SD + cc + 1] = x1;
            } else {
                if (mode == 0) { x0 = fmaxf(x0, 0.f); x1 = fmaxf(x1, 0.f); }
                else if (mode == 1) { x0 = tanh_fast(x0); x1 = tanh_fast(x1); }
                else {
                    float2 hv = shw[idx*32 + lane];
                    x0 = tanh_fast(hv.x + x0); x1 = tanh_fast(hv.y + x1);
                }
                if (mode != 1) shw[idx*32 + lane] = make_float2(x0, x1);
                *(__half2*)(act + rr*AP + cc) = __halves2half2(__float2half_rn(x0),
                                                               __float2half_rn(x1));
            }
        }
    }
    if (mode != 3) GBAR(wm + 1);           // act rows visible to wm-group
}

// ---------------- main: 64 rows/CTA, 256 threads, 2 CTAs/SM ----------------
extern "C" __global__ void __launch_bounds__(256, 2)
ode_mma_full(const float* __restrict__ state,
             const float* __restrict__ blkb1, const float* __restrict__ blkb2,
             float* __restrict__ out)
{
    extern __shared__ char smem[];
    float2* s_h  = (float2*)(smem + OFF_H);
    __half* act  = (__half*)(smem + OFF_ACT);
    const uint32_t actu = s2u(act);
    const int tid = threadIdx.x, lane = tid & 31, wid = tid >> 5;
    const int wm = wid & 1, wn = wid >> 1;   // 2 (M) x 4 (N) warp grid
    const size_t row0 = (size_t)blockIdx.x * MROWS;
    const float* st = state + row0 * SD;
    float2* shw = s_h + wid * 1024;          // per-warp 8KB fragment region

    const uint32_t arow0 = (uint32_t)(((32*wm + (lane & 15))*AP + ((lane >> 4) << 3)) * 2);
    const uint32_t arow1 = arow0 + (uint32_t)(16*AP*2);
    const uint4* bw = (const uint4*)g_Wf + wn*128 + lane;

    const int sub = wn*32 + lane;            // group-local col index 0..127

    // act init: col-loop, no div/mod
    #pragma unroll 4
    for (int r = 0; r < 32; r++) {
        int rr = 32*wm + r;
        act[rr*AP + sub] = __float2half_rn(sub < SD ? st[rr*SD + sub] : 0.f);
        if (sub < 16) {
            int c = 128 + sub;
            act[rr*AP + c] = __float2half_rn(c < SD ? st[rr*SD + c] : 0.f);
        }
    }
    GBAR(wm + 1);

    float d[2][8][4];

    gemm<9>(bw, actu, arow0, arow1, d, 1);
    epilogue(0, g_b0p, d, act, shw, nullptr, wm, wn, lane);

    for (int b = 0; b < 4; b++) {
        gemm<16>(bw + (size_t)(9 + 32*b)*512, actu, arow0, arow1, d, 1);
        epilogue(1, blkb1 + b*256, d, act, shw, nullptr, wm, wn, lane);
        gemm<16>(bw + (size_t)(9 + 32*b + 16)*512, actu, arow0, arow1, d, 1);
        epilogue(2, blkb2 + b*256, d, act, shw, nullptr, wm, wn, lane);
    }

    gemm<16>(bw + (size_t)137*512, actu, arow0, arow1, d, 1);

    GBAR(wm + 1);                            // Wout GEMM done reading act rows
    #pragma unroll 4
    for (int r = 0; r < 32; r++) {
        int rr = 32*wm + r;
        act[rr*AP + sub] = __float2half_rn(sub < SD ? st[rr*SD + sub] : 0.f);
        if (sub < 16) {
            int c = 128 + sub;
            act[rr*AP + c] = __float2half_rn(c < SD ? st[rr*SD + c] : 0.f);
        }
    }
    GBAR(wm + 1);

    gemm<9>(bw + (size_t)153*512, actu, arow0, arow1, d, 0);
    epilogue(3, g_bias2, d, act, shw, out + row0*SD, wm, wn, lane);
}

extern "C" void kernel_launch(void* const* d_in, const int* in_sizes, int n_in,
                              void* d_out, int out_size) {
    const float* t        = (const float*)d_in[0];
    const float* state    = (const float*)d_in[1];
    const float* W0       = (const float*)d_in[2];
    const float* b0       = (const float*)d_in[3];
    const float* blkW1    = (const float*)d_in[4];
    const float* blkb1    = (const float*)d_in[5];
    const float* blkW2    = (const float*)d_in[6];
    const float* blkb2    = (const float*)d_in[7];
    const float* Wout     = (const float*)d_in[8];
    const float* bout     = (const float*)d_in[9];
    const float* lm_in_w  = (const float*)d_in[10];
    const float* lm_in_b  = (const float*)d_in[11];
    const float* lm_out_w = (const float*)d_in[12];
    const float* lm_out_b = (const float*)d_in[13];
    const float* ta_in_w  = (const float*)d_in[14];
    const float* ta_in_b  = (const float*)d_in[15];
    const float* ta_out_w = (const float*)d_in[16];
    const float* ta_out_b = (const float*)d_in[17];
    float* out = (float*)d_out;

    cudaFuncSetAttribute(ode_mma_full, cudaFuncAttributeMaxDynamicSharedMemorySize, SMEM_SZ);
    prep1<<<1, 256>>>(t, W0, b0, bout, lm_in_w, lm_in_b, lm_out_w, lm_out_b,
                      ta_in_b, ta_out_w, ta_out_b);
    prepW<<<77, 256>>>(ta_in_w, ta_out_w, lm_in_w, lm_out_w);
    prepW2<<<2624, 256>>>(W0, blkW1, blkW2, Wout);
    ode_mma_full<<<131072 / MROWS, 256, SMEM_SZ>>>(state, blkb1, blkb2, out);
}

// round 16
// speedup vs baseline: 1.9833x; 1.2122x over previous
#include <cuda_runtime.h>
#include <cuda_fp16.h>
#include <cstdint>

#define SD   137
#define HIDN 256
#define AP   264
#define MROWS 32
#define OFF_H   0                      // s_h per-warp frag layout, 32768 B
#define OFF_ACT 32768                  // act fp16 [32][264] = 16896 B
#define SMEM_SZ (OFF_ACT + 16896)      // 49664 -> 3 CTAs/SM

#define NCHUNK 162
__device__ float g_b0p[HIDN];
__device__ float g_Waug[144*136];
__device__ float g_bias2[144];
// fragment order: [chunk][wq(8)][p(2)][lane(32)][8 halves]  (chunk = 512 uint4)
__device__ __align__(16) __half g_Wf[(NCHUNK+2)*4096];

__device__ __forceinline__ float tanh_fast(float x){
    float e = __expf(2.f*x); return 1.f - __fdividef(2.f, e + 1.f);
}
__device__ __forceinline__ uint32_t s2u(const void* p){
    uint32_t a;
    asm("{ .reg .u64 t; cvta.to.shared.u64 t, %1; cvt.u32.u64 %0, t; }" : "=r"(a) : "l"(p));
    return a;
}
#define MMA(d, a0, a1, a2, a3, b0, b1) asm volatile( \
    "mma.sync.aligned.m16n8k16.row.col.f32.f16.f16.f32 " \
    "{%0,%1,%2,%3}, {%4,%5,%6,%7}, {%8,%9}, {%0,%1,%2,%3};" \
    : "+f"((d)[0]), "+f"((d)[1]), "+f"((d)[2]), "+f"((d)[3]) \
    : "r"(a0), "r"(a1), "r"(a2), "r"(a3), "r"(b0), "r"(b1))
#define LDM4(r, addr) asm volatile( \
    "ldmatrix.sync.aligned.m8n8.x4.shared.b16 {%0,%1,%2,%3}, [%4];" \
    : "=r"((r)[0]), "=r"((r)[1]), "=r"((r)[2]), "=r"((r)[3]) : "r"(addr))
#define PF_L1(p) asm volatile("prefetch.global.L1 [%0];" :: "l"(p))

// 8 MMAs of one chunk (2 mi x 4 ni) against 2 B quads
#define MMA8(d, a0, a1, q0, q1) do { \
    MMA(d[0][0], a0[0],a0[1],a0[2],a0[3], q0.x, q0.y); \
    MMA(d[1][0], a1[0],a1[1],a1[2],a1[3], q0.x, q0.y); \
    MMA(d[0][1], a0[0],a0[1],a0[2],a0[3], q0.z, q0.w); \
    MMA(d[1][1], a1[0],a1[1],a1[2],a1[3], q0.z, q0.w); \
    MMA(d[0][2], a0[0],a0[1],a0[2],a0[3], q1.x, q1.y); \
    MMA(d[1][2], a1[0],a1[1],a1[2],a1[3], q1.x, q1.y); \
    MMA(d[0][3], a0[0],a0[1],a0[2],a0[3], q1.z, q1.w); \
    MMA(d[1][3], a1[0],a1[1],a1[2],a1[3], q1.z, q1.w); \
} while(0)

// ---------------- prep ----------------
__global__ void prep1(const float* __restrict__ t, const float* __restrict__ W0,
                      const float* __restrict__ b0, const float* __restrict__ bout,
                      const float* __restrict__ lm_in_w, const float* __restrict__ lm_in_b,
                      const float* __restrict__ lm_out_w, const float* __restrict__ lm_out_b,
                      const float* __restrict__ ta_in_b,
                      const float* __restrict__ ta_out_w, const float* __restrict__ ta_out_b){
    int i = threadIdx.x;
    float ang = t[0] * (2.0f * 3.14159265358979323846f / 24.0f);
    g_b0p[i] = b0[i] + sinf(ang)*W0[i*139+137] + cosf(ang)*W0[i*139+138];
    if (i < 128) {
        float a = ta_out_b[i];
        for (int k = 0; k < 128; k++) a += ta_out_w[i*128+k] * ta_in_b[256+k];
        g_bias2[i] = bout[i] + 0.1f*a;
    } else if (i < 136) {
        int j = i - 128;
        float a = lm_out_b[j];
        for (int k = 0; k < 8; k++) a += lm_out_w[j*8+k] * lm_in_b[16+k];
        g_bias2[i] = bout[i] + 0.1f*a;
    } else if (i < 144) {
        g_bias2[i] = (i == 136) ? bout[136] : 0.f;
    }
}

__global__ void prepW(const float* __restrict__ ta_in_w, const float* __restrict__ ta_out_w,
                      const float* __restrict__ lm_in_w, const float* __restrict__ lm_out_w){
    int idx = blockIdx.x*blockDim.x + threadIdx.x;
    if (idx >= 144*136) return;
    int n = idx / 136, k = idx - n*136;
    float v = 0.f;
    if (n < 128 && k < 128) {
        for (int m = 0; m < 128; m++) v += ta_out_w[n*128+m] * ta_in_w[(256+m)*128+k];
    } else if (n >= 128 && n < 136 && k >= 128) {
        for (int m = 0; m < 8; m++) v += lm_out_w[(n-128)*8+m] * lm_in_w[(16+m)*8+(k-128)];
    }
    if (n == k && n < 136) v -= 1.f;
    g_Waug[idx] = 0.1f * v;
}

// weights -> fp16, fragment order for 8x2 layout (pad chunks zeroed)
__global__ void prepW2(const float* __restrict__ W0, const float* __restrict__ W1,
                       const float* __restrict__ W2, const float* __restrict__ Wout){
    int idx = blockIdx.x*blockDim.x + threadIdx.x;
    if (idx >= (NCHUNK+2)*4096) return;
    int c = idx >> 12, e = idx & 4095;
    if (c >= NCHUNK) { g_Wf[idx] = __float2half_rn(0.f); return; }
    int wq = e >> 9, p = (e >> 8) & 1, l = (e >> 3) & 31, j = e & 7;
    int r0 = l >> 2, kk2 = (l & 3) * 2;
    int ni = 2*p + (j >> 2), jj = j & 3;
    int n = 32*wq + 8*ni + r0;
    int kloc = kk2 + (jj & 1) + 8*(jj >> 1);

    const float* W; int ldw, nvalid, kmax, ci;
    if (c < 9)        { W = W0; ldw = 139; nvalid = 256; kmax = 137; ci = c; }
    else if (c < 137) { int cc = c - 9, b = cc >> 5, r = cc & 31;
                        W = (r < 16 ? W1 : W2) + b*65536; ci = r & 15;
                        ldw = 256; nvalid = 256; kmax = 256; }
    else if (c < 153) { W = Wout;   ldw = 256; nvalid = 137; kmax = 256; ci = c - 137; }
    else              { W = g_Waug; ldw = 136; nvalid = 144; kmax = 136; ci = c - 153; }
    int k = ci*16 + kloc;
    g_Wf[idx] = __float2half_rn((n < nvalid && k < kmax) ? W[n*ldw + k] : 0.f);
}

// ---------------- GEMM: unroll-2, alternating reg buffers, PF distance 2 ----------------
// chunk stride in g_Wf = 512 uint4; per-warp B footprint = 2 uint4/chunk
template<int NCH>
__device__ __forceinline__ void gemm(const uint4* __restrict__ bp,
    uint32_t ka0, uint32_t ka1, float (*d)[4][4], int fresh)
{
    if (fresh)
        #pragma unroll
        for (int mi = 0; mi < 2; mi++)
            #pragma unroll
            for (int ni = 0; ni < 4; ni++)
                #pragma unroll
                for (int e = 0; e < 4; e++) d[mi][ni][e] = 0.f;

    const uint4* p = bp;
    uint4 c0 = __ldg(p), c1 = __ldg(p + 32);
    PF_L1(p + 512); PF_L1(p + 544);

    #pragma unroll 1
    for (int ci = 0; ci < NCH/2; ci++) {
        PF_L1(p + 1024); PF_L1(p + 1056);
        uint4 n0 = __ldg(p + 512), n1 = __ldg(p + 544);
        uint32_t a0[4], a1[4];
        LDM4(a0, ka0); LDM4(a1, ka1);
        MMA8(d, a0, a1, c0, c1);
        PF_L1(p + 1536); PF_L1(p + 1568);
        c0 = __ldg(p + 1024); c1 = __ldg(p + 1056);
        LDM4(a0, ka0 + 32); LDM4(a1, ka1 + 32);
        MMA8(d, a0, a1, n0, n1);
        ka0 += 64; ka1 += 64;
        p += 1024;
    }
    if (NCH & 1) {
        uint32_t a0[4], a1[4];
        LDM4(a0, ka0); LDM4(a1, ka1);
        MMA8(d, a0, a1, c0, c1);
    }
}

// mode: 0 relu->h+act, 1 tanh->act, 2 tanh(h+.)->h+act, 3 final store
__device__ __forceinline__ void epilogue(int mode, const float* __restrict__ bias,
    float (*d)[4][4], __half* __restrict__ act, float2* __restrict__ shw,
    float* __restrict__ outp, int wq, int lane)
{
    __syncthreads();                       // all warps done reading act
    const int r0 = lane >> 2, tg = lane & 3;
    #pragma unroll
    for (int mi = 0; mi < 2; mi++)
    #pragma unroll
    for (int ni = 0; ni < 4; ni++) {
        const int cc = 32*wq + 8*ni + tg*2;
        const float b0v = bias[cc], b1v = bias[cc + 1];
        #pragma unroll
        for (int half = 0; half < 2; half++) {
            int rr = 16*mi + r0 + half*8;
            int idx = mi*8 + ni*2 + half;
            float x0 = d[mi][ni][2*half]     + b0v;
            float x1 = d[mi][ni][2*half + 1] + b1v;
            if (mode == 3) {
                if (cc < SD)     outp[rr*SD + cc]     = x0;
                if (cc + 1 < SD) outp[rr*SD + cc + 1] = x1;
            } else {
                if (mode == 0) { x0 = fmaxf(x0, 0.f); x1 = fmaxf(x1, 0.f); }
                else if (mode == 1) { x0 = tanh_fast(x0); x1 = tanh_fast(x1); }
                else {
                    float2 hv = shw[idx*32 + lane];
                    x0 = tanh_fast(hv.x + x0); x1 = tanh_fast(hv.y + x1);
                }
                if (mode != 1) shw[idx*32 + lane] = make_float2(x0, x1);
                *(__half2*)(act + rr*AP + cc) = __halves2half2(__float2half_rn(x0),
                                                               __float2half_rn(x1));
            }
        }
    }
    if (mode != 3) __syncthreads();        // act writes visible
}

// ---------------- main: 32 rows/CTA, 256 threads, 3 CTAs/SM ----------------
extern "C" __global__ void __launch_bounds__(256, 3)
ode_mma_full(const float* __restrict__ state,
             const float* __restrict__ blkb1, const float* __restrict__ blkb2,
             float* __restrict__ out)
{
    extern __shared__ char smem[];
    float2* s_h  = (float2*)(smem + OFF_H);
    __half* act  = (__half*)(smem + OFF_ACT);
    const uint32_t actu = s2u(act);
    const int tid = threadIdx.x, lane = tid & 31, wq = tid >> 5;
    const size_t row0 = (size_t)blockIdx.x * MROWS;
    const float* st = state + row0 * SD;
    float2* shw = s_h + wq * 512;          // per-warp 4KB fragment region

    const uint32_t arow0 = actu + (uint32_t)((((lane & 15))*AP + ((lane >> 4) << 3)) * 2);
    const uint32_t arow1 = arow0 + (uint32_t)(16*AP*2);
    const uint4* bw = (const uint4*)g_Wf + wq*64 + lane;

    // act init: cols 0..143 (zero-padded beyond SD), rows 0..31
    if (tid < 144) {
        #pragma unroll 4
        for (int r = 0; r < 32; r++)
            act[r*AP + tid] = __float2half_rn(tid < SD ? st[r*SD + tid] : 0.f);
    }
    __syncthreads();

    float d[2][4][4];

    gemm<9>(bw, arow0, arow1, d, 1);
    epilogue(0, g_b0p, d, act, shw, nullptr, wq, lane);

    for (int b = 0; b < 4; b++) {
        gemm<16>(bw + (size_t)(9 + 32*b)*512, arow0, arow1, d, 1);
        epilogue(1, blkb1 + b*256, d, act, shw, nullptr, wq, lane);
        gemm<16>(bw + (size_t)(9 + 32*b + 16)*512, arow0, arow1, d, 1);
        epilogue(2, blkb2 + b*256, d, act, shw, nullptr, wq, lane);
    }

    gemm<16>(bw + (size_t)137*512, arow0, arow1, d, 1);

    __syncthreads();                       // Wout GEMM done reading act
    if (tid < 144) {
        #pragma unroll 4
        for (int r = 0; r < 32; r++)
            act[r*AP + tid] = __float2half_rn(tid < SD ? st[r*SD + tid] : 0.f);
    }
    __syncthreads();

    gemm<9>(bw + (size_t)153*512, arow0, arow1, d, 0);
    epilogue(3, g_bias2, d, act, shw, out + row0*SD, wq, lane);
}

extern "C" void kernel_launch(void* const* d_in, const int* in_sizes, int n_in,
                              void* d_out, int out_size) {
    const float* t        = (const float*)d_in[0];
    const float* state    = (const float*)d_in[1];
    const float* W0       = (const float*)d_in[2];
    const float* b0       = (const float*)d_in[3];
    const float* blkW1    = (const float*)d_in[4];
    const float* blkb1    = (const float*)d_in[5];
    const float* blkW2    = (const float*)d_in[6];
    const float* blkb2    = (const float*)d_in[7];
    const float* Wout     = (const float*)d_in[8];
    const float* bout     = (const float*)d_in[9];
    const float* lm_in_w  = (const float*)d_in[10];
    const float* lm_in_b  = (const float*)d_in[11];
    const float* lm_out_w = (const float*)d_in[12];
    const float* lm_out_b = (const float*)d_in[13];
    const float* ta_in_w  = (const float*)d_in[14];
    const float* ta_in_b  = (const float*)d_in[15];
    const float* ta_out_w = (const float*)d_in[16];
    const float* ta_out_b = (const float*)d_in[17];
    float* out = (float*)d_out;

    cudaFuncSetAttribute(ode_mma_full, cudaFuncAttributeMaxDynamicSharedMemorySize, SMEM_SZ);
    prep1<<<1, 256>>>(t, W0, b0, bout, lm_in_w, lm_in_b, lm_out_w, lm_out_b,
                      ta_in_b, ta_out_w, ta_out_b);
    prepW<<<77, 256>>>(ta_in_w, ta_out_w, lm_in_w, lm_out_w);
    prepW2<<<2624, 256>>>(W0, blkW1, blkW2, Wout);
    ode_mma_full<<<131072 / MROWS, 256, SMEM_SZ>>>(state, blkb1, blkb2, out);
}